// round 4
// baseline (speedup 1.0000x reference)
#include <cuda_runtime.h>
#include <cuda_bf16.h>

// LIF recurrence over T=4 steps.
// x: [T=4, B=64, C=128, H=32, W=32] fp32; mem0: [1, C, H, W] fp32 (B-broadcast)
// out: [T, B, C, H, W] fp32 in {0,1}
// Per element: mem = tau*mem + x[t]; s = (mem > v_th); mem = s ? 0 : mem.
//
// HBM-bound. Persistent single-wave grid (152 SMs x 4 CTAs x 512 thr),
// grid-stride loop: no wave transitions, continuous DRAM request stream.
// Evict-first loads/stores keep the two 134MB streams from thrashing L2.

#define TAU 0.25f
#define V_TH 1.0f

__device__ __forceinline__ void lif_step(float4& mem, const float4& xt, float4& s) {
    mem.x = TAU * mem.x + xt.x; s.x = (mem.x > V_TH) ? 1.0f : 0.0f; mem.x = (mem.x > V_TH) ? 0.0f : mem.x;
    mem.y = TAU * mem.y + xt.y; s.y = (mem.y > V_TH) ? 1.0f : 0.0f; mem.y = (mem.y > V_TH) ? 0.0f : mem.y;
    mem.z = TAU * mem.z + xt.z; s.z = (mem.z > V_TH) ? 1.0f : 0.0f; mem.z = (mem.z > V_TH) ? 0.0f : mem.z;
    mem.w = TAU * mem.w + xt.w; s.w = (mem.w > V_TH) ? 1.0f : 0.0f; mem.w = (mem.w > V_TH) ? 0.0f : mem.w;
}

__global__ __launch_bounds__(512) void lif_kernel(
    const float4* __restrict__ x,
    const float4* __restrict__ mem0,
    float4* __restrict__ out,
    int n4)          // float4 units per timestep: B*C*H*W/4 = 2,097,152
{
    const int CHW4_MASK = 32767;   // CHW/4 = 2^15, mask for B-broadcast of mem0
    int stride = gridDim.x * blockDim.x;

    for (int i = blockIdx.x * blockDim.x + threadIdx.x; i < n4; i += stride) {
        float4 mem = __ldg(&mem0[i & CHW4_MASK]);

        // 4 independent evict-first loads issue back-to-back (MLP=4/thread).
        float4 x0 = __ldcs(&x[0 * (size_t)n4 + i]);
        float4 x1 = __ldcs(&x[1 * (size_t)n4 + i]);
        float4 x2 = __ldcs(&x[2 * (size_t)n4 + i]);
        float4 x3 = __ldcs(&x[3 * (size_t)n4 + i]);

        float4 s;
        lif_step(mem, x0, s); __stcs(&out[0 * (size_t)n4 + i], s);
        lif_step(mem, x1, s); __stcs(&out[1 * (size_t)n4 + i], s);
        lif_step(mem, x2, s); __stcs(&out[2 * (size_t)n4 + i], s);
        lif_step(mem, x3, s); __stcs(&out[3 * (size_t)n4 + i], s);
    }
}

extern "C" void kernel_launch(void* const* d_in, const int* in_sizes, int n_in,
                              void* d_out, int out_size) {
    const float4* x    = (const float4*)d_in[0];   // [4, 64, 128, 32, 32]
    const float4* mem0 = (const float4*)d_in[1];   // [1, 128, 32, 32]
    float4* out = (float4*)d_out;

    int n_per_t = in_sizes[0] / 4;       // 8,388,608 elems per timestep
    int n4 = n_per_t / 4;                // 2,097,152 float4 units

    // Single persistent wave: 152 SMs x 4 CTAs/SM (32 regs, 512 thr -> fits 4).
    int threads = 512;
    int blocks = 152 * 4;                // 608
    lif_kernel<<<blocks, threads>>>(x, mem0, out, n4);
}

// round 5
// speedup vs baseline: 1.0516x; 1.0516x over previous
#include <cuda_runtime.h>
#include <cuda_bf16.h>

// LIF recurrence over T=4 steps.
// x: [T=4, B=64, C=128, H=32, W=32] fp32; mem0: [1, C, H, W] fp32 (B-broadcast)
// out: [T, B, C, H, W] fp32 in {0,1}
// Per element: mem = tau*mem + x[t]; s = (mem > v_th); mem = s ? 0 : mem.
//
// HBM-bound. 1 float4/thread, 512-thread blocks, single-shot grid (no
// grid-stride loop: front-batched loads, no loop-carried register reuse).
// Loads are evict-first streaming; stores use default writeback so L2
// aggregates full lines and drains to DRAM in scheduled bursts.

#define TAU 0.25f
#define V_TH 1.0f

__device__ __forceinline__ void lif_step(float4& mem, const float4& xt, float4& s) {
    mem.x = TAU * mem.x + xt.x; s.x = (mem.x > V_TH) ? 1.0f : 0.0f; mem.x = (mem.x > V_TH) ? 0.0f : mem.x;
    mem.y = TAU * mem.y + xt.y; s.y = (mem.y > V_TH) ? 1.0f : 0.0f; mem.y = (mem.y > V_TH) ? 0.0f : mem.y;
    mem.z = TAU * mem.z + xt.z; s.z = (mem.z > V_TH) ? 1.0f : 0.0f; mem.z = (mem.z > V_TH) ? 0.0f : mem.z;
    mem.w = TAU * mem.w + xt.w; s.w = (mem.w > V_TH) ? 1.0f : 0.0f; mem.w = (mem.w > V_TH) ? 0.0f : mem.w;
}

__global__ __launch_bounds__(512) void lif_kernel(
    const float4* __restrict__ x,
    const float4* __restrict__ mem0,
    float4* __restrict__ out,
    int n4)          // float4 units per timestep: B*C*H*W/4 = 2,097,152
{
    int i = blockIdx.x * blockDim.x + threadIdx.x;
    if (i >= n4) return;

    // CHW/4 = 128*32*32/4 = 32768 = 2^15 -> mask for B-broadcast of mem0
    const int CHW4_MASK = 32767;
    float4 mem = __ldg(&mem0[i & CHW4_MASK]);

    // Front-batch the 4 streaming loads (evict-first), 64 B in flight/thread.
    float4 x0 = __ldcs(&x[0 * (size_t)n4 + i]);
    float4 x1 = __ldcs(&x[1 * (size_t)n4 + i]);
    float4 x2 = __ldcs(&x[2 * (size_t)n4 + i]);
    float4 x3 = __ldcs(&x[3 * (size_t)n4 + i]);

    float4 s;
    lif_step(mem, x0, s); out[0 * (size_t)n4 + i] = s;
    lif_step(mem, x1, s); out[1 * (size_t)n4 + i] = s;
    lif_step(mem, x2, s); out[2 * (size_t)n4 + i] = s;
    lif_step(mem, x3, s); out[3 * (size_t)n4 + i] = s;
}

extern "C" void kernel_launch(void* const* d_in, const int* in_sizes, int n_in,
                              void* d_out, int out_size) {
    const float4* x    = (const float4*)d_in[0];   // [4, 64, 128, 32, 32]
    const float4* mem0 = (const float4*)d_in[1];   // [1, 128, 32, 32]
    float4* out = (float4*)d_out;

    int n_per_t = in_sizes[0] / 4;       // 8,388,608 elems per timestep
    int n4 = n_per_t / 4;                // 2,097,152 float4 units

    int threads = 512;
    int blocks = (n4 + threads - 1) / threads;   // 4096
    lif_kernel<<<blocks, threads>>>(x, mem0, out, n4);
}

// round 6
// speedup vs baseline: 1.0941x; 1.0404x over previous
#include <cuda_runtime.h>
#include <cuda_bf16.h>

// LIF recurrence over T=4 steps.
// x: [T=4, B=64, C=128, H=32, W=32] fp32; mem0: [1, C, H, W] fp32 (B-broadcast)
// out: [T, B, C, H, W] fp32 in {0,1}
// Per element: mem = tau*mem + x[t]; s = (mem > v_th); mem = s ? 0 : mem.
//
// HBM-bound, near the mixed R/W floor. 1 float4/thread, one-shot grid.
// Phase structure per thread: 4 batched evict-first LDG.128 -> pure FMA
// chain for all 4 steps -> 4 back-to-back evict-first STG.128. This keeps
// store issue off the FMA critical path and presents cleaner read/write
// bursts to DRAM.

#define TAU 0.25f
#define V_TH 1.0f

__device__ __forceinline__ void lif_step(float4& mem, const float4& xt, float4& s) {
    mem.x = TAU * mem.x + xt.x; s.x = (mem.x > V_TH) ? 1.0f : 0.0f; mem.x = (mem.x > V_TH) ? 0.0f : mem.x;
    mem.y = TAU * mem.y + xt.y; s.y = (mem.y > V_TH) ? 1.0f : 0.0f; mem.y = (mem.y > V_TH) ? 0.0f : mem.y;
    mem.z = TAU * mem.z + xt.z; s.z = (mem.z > V_TH) ? 1.0f : 0.0f; mem.z = (mem.z > V_TH) ? 0.0f : mem.z;
    mem.w = TAU * mem.w + xt.w; s.w = (mem.w > V_TH) ? 1.0f : 0.0f; mem.w = (mem.w > V_TH) ? 0.0f : mem.w;
}

__global__ __launch_bounds__(512) void lif_kernel(
    const float4* __restrict__ x,
    const float4* __restrict__ mem0,
    float4* __restrict__ out,
    int n4)          // float4 units per timestep: B*C*H*W/4 = 2,097,152
{
    int i = blockIdx.x * blockDim.x + threadIdx.x;
    if (i >= n4) return;

    // CHW/4 = 128*32*32/4 = 32768 = 2^15 -> mask for B-broadcast of mem0
    const int CHW4_MASK = 32767;
    float4 mem = __ldg(&mem0[i & CHW4_MASK]);

    // Phase 1: front-batch the 4 streaming loads (evict-first).
    float4 x0 = __ldcs(&x[0 * (size_t)n4 + i]);
    float4 x1 = __ldcs(&x[1 * (size_t)n4 + i]);
    float4 x2 = __ldcs(&x[2 * (size_t)n4 + i]);
    float4 x3 = __ldcs(&x[3 * (size_t)n4 + i]);

    // Phase 2: pure compute, all 4 steps.
    float4 s0, s1, s2, s3;
    lif_step(mem, x0, s0);
    lif_step(mem, x1, s1);
    lif_step(mem, x2, s2);
    lif_step(mem, x3, s3);

    // Phase 3: back-to-back streaming stores.
    __stcs(&out[0 * (size_t)n4 + i], s0);
    __stcs(&out[1 * (size_t)n4 + i], s1);
    __stcs(&out[2 * (size_t)n4 + i], s2);
    __stcs(&out[3 * (size_t)n4 + i], s3);
}

extern "C" void kernel_launch(void* const* d_in, const int* in_sizes, int n_in,
                              void* d_out, int out_size) {
    const float4* x    = (const float4*)d_in[0];   // [4, 64, 128, 32, 32]
    const float4* mem0 = (const float4*)d_in[1];   // [1, 128, 32, 32]
    float4* out = (float4*)d_out;

    int n_per_t = in_sizes[0] / 4;       // 8,388,608 elems per timestep
    int n4 = n_per_t / 4;                // 2,097,152 float4 units

    int threads = 512;
    int blocks = (n4 + threads - 1) / threads;   // 4096
    lif_kernel<<<blocks, threads>>>(x, mem0, out, n4);
}